// round 5
// baseline (speedup 1.0000x reference)
#include <cuda_runtime.h>
#include <math.h>
#include <stdint.h>

// ---------------- problem constants ----------------
#define BSZ 2
#define CH  64
#define NPT 400
#define LT  12
#define DM  128
#define NH  8
#define HDM 16
#define FFD 1024

#define NTOK (BSZ*LT*NPT)          // 9600 tokens (b,l,n)
#define NROW (BSZ*NH*LT*NPT)       // 76800 attention rows (b,h,l,n)
#define OUT0 (BSZ*CH*NPT*LT)       // 614400

#define EPS_LN 1e-5f
#define NEG_INF (__int_as_float(0xff800000))

// ---------------- scratch (device globals, no allocation) ----------------
__device__ float g_q1[NTOK*DM];
__device__ float g_q2[NTOK*DM];
__device__ float g_k1[NTOK*DM];
__device__ float g_k2[NTOK*DM];
__device__ float g_v [NTOK*DM];
__device__ float g_aout[NTOK*DM];
__device__ float g_mx [NROW];
__device__ float g_t1 [NROW];
__device__ float g_t2 [NROW];
__device__ float g_is1[NROW];
__device__ float g_is2[NROW];

// =====================================================================
// Kernel 1: projections + per-head l2 norm.
// block = one token, 160 threads = 5 warps (one per projection),
// each warp: 32 lanes x 4 outputs (float4).
// =====================================================================
__global__ __launch_bounds__(160) void k1_proj(
    const float* __restrict__ x, const float* __restrict__ xa1, const float* __restrict__ xa2,
    const float* __restrict__ WQ1, const float* __restrict__ bQ1,
    const float* __restrict__ WQ2, const float* __restrict__ bQ2,
    const float* __restrict__ WK1, const float* __restrict__ bK1,
    const float* __restrict__ WK2, const float* __restrict__ bK2,
    const float* __restrict__ WV,  const float* __restrict__ bV)
{
    int t = blockIdx.x;
    int b = t / (LT*NPT); int rem = t % (LT*NPT);
    int l = rem / NPT;    int n = rem % NPT;
    __shared__ float sh[3*CH];     // [x | xa1 | xa2]
    int tid = threadIdx.x;
    for (int idx = tid; idx < 3*CH; idx += 160) {
        int arr = idx >> 6, c = idx & 63;
        const float* src = (arr == 0) ? x : (arr == 1 ? xa1 : xa2);
        sh[idx] = src[((size_t)(b*CH + c)*NPT + n)*LT + l];
    }
    __syncthreads();

    int p = tid >> 5, dg = tid & 31;       // p uniform per warp
    const float* W    = (p==0)?WQ1 : (p==1)?WQ2 : (p==2)?WK1 : (p==3)?WK2 : WV;
    const float* bias = (p==0)?bQ1 : (p==1)?bQ2 : (p==2)?bK1 : (p==3)?bK2 : bV;
    int soff = (p==0) ? CH : (p==1 ? 2*CH : 0);

    float4 acc = *(const float4*)&bias[4*dg];
    #pragma unroll 4
    for (int c = 0; c < CH; c++) {
        float xv = sh[soff + c];
        float4 w = *(const float4*)&W[c*DM + 4*dg];
        acc.x += xv*w.x; acc.y += xv*w.y; acc.z += xv*w.z; acc.w += xv*w.w;
    }
    if (p < 4) {  // l2norm per head (head = 16 dims = 4 consecutive lanes)
        float ss = acc.x*acc.x + acc.y*acc.y + acc.z*acc.z + acc.w*acc.w;
        ss += __shfl_xor_sync(0xffffffffu, ss, 1);
        ss += __shfl_xor_sync(0xffffffffu, ss, 2);
        float inv = 1.0f / fmaxf(sqrtf(ss), 1e-12f);
        acc.x *= inv; acc.y *= inv; acc.z *= inv; acc.w *= inv;
    }
    float* dst = (p==0)?g_q1 : (p==1)?g_q2 : (p==2)?g_k1 : (p==3)?g_k2 : g_v;
    *(float4*)&dst[(size_t)t*DM + 4*dg] = acc;
}

// =====================================================================
// Kernel 2: attn[b,h,l,n,m] = temp[h]*(q1.k1 + q2.k2), written to d_out.
// grid = (49 tiles, 192 bhl), block 256, 64x64 tile, 4x4 per thread.
// =====================================================================
__global__ __launch_bounds__(256) void k2_attn(
    float* __restrict__ attn, const float* __restrict__ temperature)
{
    int tile = blockIdx.x;
    int nb = tile / 7, mb = tile % 7;
    int bhl = blockIdx.y;
    int b = bhl / (NH*LT); int h = (bhl / LT) % NH; int l = bhl % LT;
    int baset = (b*LT + l)*NPT;

    __shared__ float Qs[64*33];
    __shared__ float Ks[64*33];
    int tid = threadIdx.x;

    for (int idx = tid; idx < 64*32; idx += 256) {
        int row = idx >> 5, kk = idx & 31;
        int n = nb*64 + row, m = mb*64 + row;
        float qv = 0.f, kv = 0.f;
        if (n < NPT) {
            size_t base = (size_t)(baset + n)*DM + h*HDM;
            qv = (kk < 16) ? g_q1[base + kk] : g_q2[base + kk - 16];
        }
        if (m < NPT) {
            size_t base = (size_t)(baset + m)*DM + h*HDM;
            kv = (kk < 16) ? g_k1[base + kk] : g_k2[base + kk - 16];
        }
        Qs[row*33 + kk] = qv;
        Ks[row*33 + kk] = kv;
    }
    __syncthreads();

    int tx = tid & 15, ty = tid >> 4;
    float acc[4][4] = {};
    #pragma unroll
    for (int kk = 0; kk < 32; kk++) {
        float qr[4], kr[4];
        #pragma unroll
        for (int i = 0; i < 4; i++) qr[i] = Qs[(ty + 16*i)*33 + kk];
        #pragma unroll
        for (int j = 0; j < 4; j++) kr[j] = Ks[(tx + 16*j)*33 + kk];
        #pragma unroll
        for (int i = 0; i < 4; i++)
            #pragma unroll
            for (int j = 0; j < 4; j++) acc[i][j] += qr[i]*kr[j];
    }

    float temp = temperature[h];
    size_t base = (size_t)bhl * NPT * NPT;
    #pragma unroll
    for (int i = 0; i < 4; i++) {
        int n = nb*64 + ty + 16*i;
        if (n >= NPT) continue;
        #pragma unroll
        for (int j = 0; j < 4; j++) {
            int m = mb*64 + tx + 16*j;
            if (m < NPT) attn[base + (size_t)n*NPT + m] = acc[i][j]*temp;
        }
    }
}

// =====================================================================
// Kernel 3: per-row top-k thresholds (k=200, k=100) via bitonic sort of
// 512 (padded -inf), masked-softmax sums, write p2_flat + row stats.
// block = one row, 256 threads.
// =====================================================================
__global__ __launch_bounds__(256) void k3_topk(
    const float* __restrict__ attn, float* __restrict__ p2out)
{
    int r = blockIdx.x;
    __shared__ float s[512];
    __shared__ float so[NPT];
    __shared__ float red[2][8];
    __shared__ float inv_sh[2];

    const float* row = attn + (size_t)r * NPT;
    int tid = threadIdx.x;

    for (int i = tid; i < 512; i += 256) {
        float v = (i < NPT) ? row[i] : NEG_INF;
        s[i] = v;
        if (i < NPT) so[i] = v;
    }
    __syncthreads();

    // bitonic sort ascending over 512
    for (int k = 2; k <= 512; k <<= 1) {
        for (int j = k >> 1; j > 0; j >>= 1) {
            int i  = 2*tid - (tid & (j - 1));   // bit j of i is clear
            int ip = i + j;
            bool asc = ((i & k) == 0);
            float a = s[i], bb = s[ip];
            if ((a > bb) == asc) { s[i] = bb; s[ip] = a; }
            __syncthreads();
        }
    }

    float t1 = s[512 - 200];   // 200th largest
    float t2 = s[512 - 100];   // 100th largest  (t2 >= t1)
    float mx = s[511];

    float l1 = 0.f, l2 = 0.f;
    for (int i = tid; i < 512; i += 256) {
        float v = s[i];
        if (v >= t1) {
            float e = __expf(v - mx);
            l1 += e;
            if (v >= t2) l2 += e;
        }
    }
    #pragma unroll
    for (int o = 16; o; o >>= 1) {
        l1 += __shfl_down_sync(0xffffffffu, l1, o);
        l2 += __shfl_down_sync(0xffffffffu, l2, o);
    }
    int wid = tid >> 5, lane = tid & 31;
    if (lane == 0) { red[0][wid] = l1; red[1][wid] = l2; }
    __syncthreads();
    if (tid == 0) {
        float s1 = 0.f, s2 = 0.f;
        #pragma unroll
        for (int w = 0; w < 8; w++) { s1 += red[0][w]; s2 += red[1][w]; }
        float i1 = 1.0f/s1, i2 = 1.0f/s2;
        inv_sh[0] = i1; inv_sh[1] = i2;
        g_mx[r] = mx; g_t1[r] = t1; g_t2[r] = t2; g_is1[r] = i1; g_is2[r] = i2;
    }
    __syncthreads();

    float inv2 = inv_sh[1];
    float* prow = p2out + (size_t)r * NPT;
    for (int i = tid; i < NPT; i += 256) {
        float v = so[i];
        prow[i] = (v >= t2) ? __expf(v - mx)*inv2 : 0.0f;
    }
}

// =====================================================================
// Kernel 4: out_attn = (al0*p1 + al1*p2) @ V, per (b,h,l).
// V tile resident in smem; weights recomputed from attn + row stats.
// block = one (b,h,l), 512 threads (32 n-groups x 16 d), 4 n-rows/thread.
// =====================================================================
__global__ __launch_bounds__(512) void k4_av(
    const float* __restrict__ attn, const float* __restrict__ alphas)
{
    int bhl = blockIdx.x;
    int b = bhl / (NH*LT); int h = (bhl / LT) % NH; int l = bhl % LT;
    int blN = (b*LT + l)*NPT;

    __shared__ float Vsh[416*16];
    __shared__ float Wsh[128*33];
    __shared__ float st_mx[128], st_t1[128], st_t2[128], st_i1[128], st_i2[128];

    int tid = threadIdx.x;

    float a0 = alphas[0], a1 = alphas[1];
    float amx = fmaxf(a0, a1);
    float e0 = __expf(a0 - amx), e1 = __expf(a1 - amx);
    float al0 = e0/(e0 + e1), al1 = e1/(e0 + e1);

    for (int idx = tid; idx < 416*16; idx += 512) {
        int m = idx >> 4, d = idx & 15;
        Vsh[idx] = (m < NPT) ? g_v[(size_t)(blN + m)*DM + h*HDM + d] : 0.f;
    }

    int d = tid & 15, ng = tid >> 4;
    int rowbase = bhl * NPT;

    for (int nb = 0; nb < 4; nb++) {
        __syncthreads();
        if (tid < 128) {
            int n = nb*128 + tid;
            if (n < NPT) {
                int rr = rowbase + n;
                st_mx[tid] = g_mx[rr]; st_t1[tid] = g_t1[rr]; st_t2[tid] = g_t2[rr];
                st_i1[tid] = g_is1[rr]; st_i2[tid] = g_is2[rr];
            }
        }
        float acc0 = 0.f, acc1 = 0.f, acc2 = 0.f, acc3 = 0.f;

        for (int mc = 0; mc < NPT; mc += 32) {
            __syncthreads();
            for (int idx = tid; idx < 128*32; idx += 512) {
                int nl = idx >> 5, ml = idx & 31;
                int n = nb*128 + nl, m = mc + ml;
                float w = 0.f;
                if (n < NPT && m < NPT) {
                    float a = attn[((size_t)(rowbase + n))*NPT + m];
                    float e = __expf(a - st_mx[nl]);
                    float p1 = (a >= st_t1[nl]) ? e*st_i1[nl] : 0.f;
                    float p2 = (a >= st_t2[nl]) ? e*st_i2[nl] : 0.f;
                    w = al0*p1 + al1*p2;
                }
                Wsh[nl*33 + ml] = w;
            }
            __syncthreads();
            #pragma unroll 8
            for (int ml = 0; ml < 32; ml++) {
                float vv = Vsh[(mc + ml)*16 + d];
                acc0 += Wsh[(ng      )*33 + ml]*vv;
                acc1 += Wsh[(ng +  32)*33 + ml]*vv;
                acc2 += Wsh[(ng +  64)*33 + ml]*vv;
                acc3 += Wsh[(ng +  96)*33 + ml]*vv;
            }
        }
        int n0 = nb*128 + ng;
        if (n0      < NPT) g_aout[(size_t)(blN + n0     )*DM + h*HDM + d] = acc0;
        if (n0 + 32 < NPT) g_aout[(size_t)(blN + n0 + 32)*DM + h*HDM + d] = acc1;
        if (n0 + 64 < NPT) g_aout[(size_t)(blN + n0 + 64)*DM + h*HDM + d] = acc2;
        if (n0 + 96 < NPT) g_aout[(size_t)(blN + n0 + 96)*DM + h*HDM + d] = acc3;
    }
}

// =====================================================================
// Kernel 5: epilogue per 8 tokens: Wo + LN1 + FF + LN2 + transposed store.
// block = 8 tokens, 256 threads.
// =====================================================================
__global__ __launch_bounds__(256) void k5_ffn(
    const float* __restrict__ x,
    const float* __restrict__ Wo,  const float* __restrict__ bo,
    const float* __restrict__ Wf1, const float* __restrict__ bf1,
    const float* __restrict__ Wf2, const float* __restrict__ bf2,
    const float* __restrict__ g1,  const float* __restrict__ be1,
    const float* __restrict__ g2,  const float* __restrict__ be2,
    float* __restrict__ outp)
{
    int t0 = blockIdx.x * 8;
    __shared__ float s_ao[8*128];   // attn out; later reused as FF2 partials [2][8][64]
    __shared__ float s_xt[8*64];    // xt, then residual s1
    __shared__ float s_r1[8*64];    // LN1 out, then residual s2
    __shared__ float s_h1[8*1024];  // FF hidden
    int tid = threadIdx.x;

    for (int idx = tid; idx < 8*128; idx += 256)
        s_ao[idx] = g_aout[(size_t)t0*DM + idx];
    for (int idx = tid; idx < 8*64; idx += 256) {
        int t = t0 + (idx >> 6), c = idx & 63;
        int b = t / (LT*NPT); int rem = t % (LT*NPT);
        int l = rem / NPT;    int n = rem % NPT;
        s_xt[idx] = x[((size_t)(b*CH + c)*NPT + n)*LT + l];
    }
    __syncthreads();

    // y = ao @ Wo + bo; s1 = xt + y
    for (int o = tid; o < 8*64; o += 256) {
        int t = o >> 6, c = o & 63;
        float acc = bo[c];
        #pragma unroll 8
        for (int dd = 0; dd < 128; dd++)
            acc += s_ao[t*128 + dd] * Wo[dd*64 + c];
        s_xt[o] += acc;
    }
    __syncthreads();

    // LN1 (warp per token; 64 feats, 2 per lane)
    {
        int w = tid >> 5, lane = tid & 31;
        float v0 = s_xt[w*64 + lane], v1 = s_xt[w*64 + 32 + lane];
        float sum = v0 + v1;
        #pragma unroll
        for (int o = 16; o; o >>= 1) sum += __shfl_xor_sync(0xffffffffu, sum, o);
        float mean = sum * (1.0f/64.0f);
        float d0 = v0 - mean, d1 = v1 - mean;
        float vs = d0*d0 + d1*d1;
        #pragma unroll
        for (int o = 16; o; o >>= 1) vs += __shfl_xor_sync(0xffffffffu, vs, o);
        float inv = rsqrtf(vs*(1.0f/64.0f) + EPS_LN);
        s_r1[w*64 + lane]      = d0*inv*g1[lane]      + be1[lane];
        s_r1[w*64 + 32 + lane] = d1*inv*g1[lane + 32] + be1[lane + 32];
    }
    __syncthreads();

    // FF1: h1 = relu(r1 @ Wf1 + bf1); Wf1 element reused across 8 tokens
    for (int ff = tid; ff < FFD; ff += 256) {
        float acc[8];
        float bb = bf1[ff];
        #pragma unroll
        for (int t = 0; t < 8; t++) acc[t] = bb;
        for (int c = 0; c < 64; c++) {
            float w = Wf1[c*FFD + ff];
            #pragma unroll
            for (int t = 0; t < 8; t++) acc[t] += s_r1[t*64 + c]*w;
        }
        #pragma unroll
        for (int t = 0; t < 8; t++) s_h1[t*1024 + ff] = fmaxf(acc[t], 0.f);
    }
    __syncthreads();

    // FF2: split ff-range in 2, tokens in 2 -> partials[2][8][64]
    float facc[4] = {0.f, 0.f, 0.f, 0.f};
    int c5  = tid & 63;
    int r4  = tid >> 6;          // 0..3
    int qh  = r4 & 1;            // ff half
    int th  = r4 >> 1;           // token half
    for (int ff = qh*512; ff < qh*512 + 512; ff++) {
        float w = Wf2[ff*64 + c5];
        #pragma unroll
        for (int tt = 0; tt < 4; tt++)
            facc[tt] += s_h1[(th*4 + tt)*1024 + ff]*w;
    }
    __syncthreads();   // done reading s_ao/s_h1 users; reuse s_ao for partials
    #pragma unroll
    for (int tt = 0; tt < 4; tt++)
        s_ao[qh*512 + (th*4 + tt)*64 + c5] = facc[tt];
    __syncthreads();

    // reduce partials + bias + residual: s2 = r1 + ff_out
    for (int o = tid; o < 8*64; o += 256) {
        int c = o & 63;
        float y2 = bf2[c] + s_ao[o] + s_ao[512 + o];
        s_r1[o] = s_r1[o] + y2;
    }
    __syncthreads();

    // LN2 + transposed store out[b,c,n,l]
    {
        int w = tid >> 5, lane = tid & 31;
        float v0 = s_r1[w*64 + lane], v1 = s_r1[w*64 + 32 + lane];
        float sum = v0 + v1;
        #pragma unroll
        for (int o = 16; o; o >>= 1) sum += __shfl_xor_sync(0xffffffffu, sum, o);
        float mean = sum * (1.0f/64.0f);
        float d0 = v0 - mean, d1 = v1 - mean;
        float vs = d0*d0 + d1*d1;
        #pragma unroll
        for (int o = 16; o; o >>= 1) vs += __shfl_xor_sync(0xffffffffu, vs, o);
        float inv = rsqrtf(vs*(1.0f/64.0f) + EPS_LN);
        float o0 = d0*inv*g2[lane]      + be2[lane];
        float o1 = d1*inv*g2[lane + 32] + be2[lane + 32];

        int t = t0 + w;
        int b = t / (LT*NPT); int rem = t % (LT*NPT);
        int l = rem / NPT;    int n = rem % NPT;
        outp[((size_t)(b*CH + lane     )*NPT + n)*LT + l] = o0;
        outp[((size_t)(b*CH + lane + 32)*NPT + n)*LT + l] = o1;
    }
}

// =====================================================================
extern "C" void kernel_launch(void* const* d_in, const int* in_sizes, int n_in,
                              void* d_out, int out_size)
{
    const float* x    = (const float*)d_in[0];
    const float* xa1  = (const float*)d_in[1];
    const float* xa2  = (const float*)d_in[2];
    const float* WQ1  = (const float*)d_in[3];  const float* bQ1 = (const float*)d_in[4];
    const float* WQ2  = (const float*)d_in[5];  const float* bQ2 = (const float*)d_in[6];
    const float* WK1  = (const float*)d_in[7];  const float* bK1 = (const float*)d_in[8];
    const float* WK2  = (const float*)d_in[9];  const float* bK2 = (const float*)d_in[10];
    const float* WV   = (const float*)d_in[11]; const float* bV  = (const float*)d_in[12];
    const float* Wo   = (const float*)d_in[13]; const float* bo  = (const float*)d_in[14];
    const float* Wf1  = (const float*)d_in[15]; const float* bf1 = (const float*)d_in[16];
    const float* Wf2  = (const float*)d_in[17]; const float* bf2 = (const float*)d_in[18];
    const float* g1   = (const float*)d_in[19]; const float* be1 = (const float*)d_in[20];
    const float* g2   = (const float*)d_in[21]; const float* be2 = (const float*)d_in[22];
    const float* temp = (const float*)d_in[23];
    const float* alph = (const float*)d_in[24];

    float* outp = (float*)d_out;
    float* attn = outp + OUT0;                               // attn_flat region
    float* p2   = outp + OUT0 + (size_t)NROW*NPT;            // p2_flat region

    k1_proj<<<NTOK, 160>>>(x, xa1, xa2, WQ1, bQ1, WQ2, bQ2,
                           WK1, bK1, WK2, bK2, WV, bV);

    dim3 g2d(49, BSZ*NH*LT);                                 // 7x7 tiles x 192 (b,h,l)
    k2_attn<<<g2d, 256>>>(attn, temp);

    k3_topk<<<NROW, 256>>>(attn, p2);

    k4_av<<<BSZ*NH*LT, 512>>>(attn, alph);

    k5_ffn<<<NTOK/8, 256>>>(x, Wo, bo, Wf1, bf1, Wf2, bf2,
                            g1, be1, g2, be2, outp);
}

// round 8
// speedup vs baseline: 1.6662x; 1.6662x over previous
#include <cuda_runtime.h>
#include <math.h>
#include <stdint.h>

// ---------------- problem constants ----------------
#define BSZ 2
#define CH  64
#define NPT 400
#define LT  12
#define DM  128
#define NH  8
#define HDM 16
#define FFD 1024

#define NTOK (BSZ*LT*NPT)          // 9600 tokens (b,l,n)
#define NROW (BSZ*NH*LT*NPT)       // 76800 attention rows (b,h,l,n)
#define OUT0 (BSZ*CH*NPT*LT)       // 614400

#define EPS_LN 1e-5f
#define NEG_INF (__int_as_float(0xff800000))

// ---------------- scratch (device globals, no allocation) ----------------
__device__ float g_q1[NTOK*DM];
__device__ float g_q2[NTOK*DM];
__device__ float g_k1[NTOK*DM];
__device__ float g_k2[NTOK*DM];
__device__ float g_v [NTOK*DM];
__device__ float g_aout[NTOK*DM];
__device__ float g_w [(size_t)NROW*NPT];   // combined attention weights (123MB)

// =====================================================================
// Kernel 1: projections + per-head l2 norm.
// block = one token, 160 threads = 5 warps (one per projection),
// each warp: 32 lanes x 4 outputs (float4).
// =====================================================================
__global__ __launch_bounds__(160) void k1_proj(
    const float* __restrict__ x, const float* __restrict__ xa1, const float* __restrict__ xa2,
    const float* __restrict__ WQ1, const float* __restrict__ bQ1,
    const float* __restrict__ WQ2, const float* __restrict__ bQ2,
    const float* __restrict__ WK1, const float* __restrict__ bK1,
    const float* __restrict__ WK2, const float* __restrict__ bK2,
    const float* __restrict__ WV,  const float* __restrict__ bV)
{
    int t = blockIdx.x;
    int b = t / (LT*NPT); int rem = t % (LT*NPT);
    int l = rem / NPT;    int n = rem % NPT;
    __shared__ float sh[3*CH];     // [x | xa1 | xa2]
    int tid = threadIdx.x;
    for (int idx = tid; idx < 3*CH; idx += 160) {
        int arr = idx >> 6, c = idx & 63;
        const float* src = (arr == 0) ? x : (arr == 1 ? xa1 : xa2);
        sh[idx] = src[((size_t)(b*CH + c)*NPT + n)*LT + l];
    }
    __syncthreads();

    int p = tid >> 5, dg = tid & 31;       // p uniform per warp
    const float* W    = (p==0)?WQ1 : (p==1)?WQ2 : (p==2)?WK1 : (p==3)?WK2 : WV;
    const float* bias = (p==0)?bQ1 : (p==1)?bQ2 : (p==2)?bK1 : (p==3)?bK2 : bV;
    int soff = (p==0) ? CH : (p==1 ? 2*CH : 0);

    float4 acc = *(const float4*)&bias[4*dg];
    #pragma unroll 4
    for (int c = 0; c < CH; c++) {
        float xv = sh[soff + c];
        float4 w = *(const float4*)&W[c*DM + 4*dg];
        acc.x += xv*w.x; acc.y += xv*w.y; acc.z += xv*w.z; acc.w += xv*w.w;
    }
    if (p < 4) {  // l2norm per head (head = 16 dims = 4 consecutive lanes)
        float ss = acc.x*acc.x + acc.y*acc.y + acc.z*acc.z + acc.w*acc.w;
        ss += __shfl_xor_sync(0xffffffffu, ss, 1);
        ss += __shfl_xor_sync(0xffffffffu, ss, 2);
        float inv = 1.0f / fmaxf(sqrtf(ss), 1e-12f);
        acc.x *= inv; acc.y *= inv; acc.z *= inv; acc.w *= inv;
    }
    float* dst = (p==0)?g_q1 : (p==1)?g_q2 : (p==2)?g_k1 : (p==3)?g_k2 : g_v;
    *(float4*)&dst[(size_t)t*DM + 4*dg] = acc;
}

// =====================================================================
// Kernel 2: attn[b,h,l,n,m] = temp[h]*(q1.k1 + q2.k2), written to d_out.
// grid = (49 tiles, 192 bhl), block 256, 64x64 tile, 4x4 per thread.
// =====================================================================
__global__ __launch_bounds__(256) void k2_attn(
    float* __restrict__ attn, const float* __restrict__ temperature)
{
    int tile = blockIdx.x;
    int nb = tile / 7, mb = tile % 7;
    int bhl = blockIdx.y;
    int b = bhl / (NH*LT); int h = (bhl / LT) % NH; int l = bhl % LT;
    int baset = (b*LT + l)*NPT;

    __shared__ float Qs[64*33];
    __shared__ float Ks[64*33];
    int tid = threadIdx.x;

    for (int idx = tid; idx < 64*32; idx += 256) {
        int row = idx >> 5, kk = idx & 31;
        int n = nb*64 + row, m = mb*64 + row;
        float qv = 0.f, kv = 0.f;
        if (n < NPT) {
            size_t base = (size_t)(baset + n)*DM + h*HDM;
            qv = (kk < 16) ? g_q1[base + kk] : g_q2[base + kk - 16];
        }
        if (m < NPT) {
            size_t base = (size_t)(baset + m)*DM + h*HDM;
            kv = (kk < 16) ? g_k1[base + kk] : g_k2[base + kk - 16];
        }
        Qs[row*33 + kk] = qv;
        Ks[row*33 + kk] = kv;
    }
    __syncthreads();

    int tx = tid & 15, ty = tid >> 4;
    float acc[4][4] = {};
    #pragma unroll
    for (int kk = 0; kk < 32; kk++) {
        float qr[4], kr[4];
        #pragma unroll
        for (int i = 0; i < 4; i++) qr[i] = Qs[(ty + 16*i)*33 + kk];
        #pragma unroll
        for (int j = 0; j < 4; j++) kr[j] = Ks[(tx + 16*j)*33 + kk];
        #pragma unroll
        for (int i = 0; i < 4; i++)
            #pragma unroll
            for (int j = 0; j < 4; j++) acc[i][j] += qr[i]*kr[j];
    }

    float temp = temperature[h];
    size_t base = (size_t)bhl * NPT * NPT;
    #pragma unroll
    for (int i = 0; i < 4; i++) {
        int n = nb*64 + ty + 16*i;
        if (n >= NPT) continue;
        #pragma unroll
        for (int j = 0; j < 4; j++) {
            int m = mb*64 + tx + 16*j;
            if (m < NPT) attn[base + (size_t)n*NPT + m] = acc[i][j]*temp;
        }
    }
}

// =====================================================================
// Kernel 3: warp-per-row exact radix select (k=200, k=100), softmax sums,
// write p2_flat AND combined weight w = al0*p1 + al1*p2 into g_w.
// block = 256 threads = 8 warps = 8 rows. No block barriers.
// =====================================================================
__device__ __forceinline__ unsigned int warp_select_kth(
    const unsigned int u[13], unsigned int k, unsigned int* hist, int lane)
{
    unsigned int prefix = 0;
    unsigned int kk = k;
    #pragma unroll
    for (int pass = 0; pass < 4; pass++) {
        int shift = 24 - 8*pass;
        unsigned int himask = (pass == 0) ? 0u : (0xFFFFFFFFu << (shift + 8));
        #pragma unroll
        for (int bq = 0; bq < 8; bq++) hist[lane*8 + bq] = 0u;
        __syncwarp();
        #pragma unroll
        for (int i = 0; i < 13; i++)
            if ((u[i] & himask) == prefix)
                atomicAdd(&hist[(u[i] >> shift) & 255u], 1u);
        __syncwarp();
        unsigned int c[8]; unsigned int lsum = 0;
        #pragma unroll
        for (int bq = 0; bq < 8; bq++) { c[bq] = hist[lane*8 + bq]; lsum += c[bq]; }
        // inclusive suffix sum over lanes (lane i gets sum of lanes >= i)
        unsigned int s = lsum;
        #pragma unroll
        for (int o = 1; o < 32; o <<= 1) {
            unsigned int tt = __shfl_down_sync(0xffffffffu, s, o);
            if (lane + o < 32) s += tt;
        }
        unsigned int excl = __shfl_down_sync(0xffffffffu, s, 1);
        if (lane == 31) excl = 0u;
        unsigned int ball = __ballot_sync(0xffffffffu,
                              (excl < kk) && (excl + lsum >= kk));
        int src = __ffs((int)ball) - 1;
        unsigned int dig = 0, nkk = 0;
        if (lane == src) {
            unsigned int cum = excl, cumsel = excl;
            int bsel = 0; bool found = false;
            #pragma unroll
            for (int bq = 7; bq >= 0; bq--) {
                if (!found && (cum + c[bq] >= kk)) { bsel = bq; cumsel = cum; found = true; }
                if (!found) cum += c[bq];
            }
            dig = (unsigned)(lane*8 + bsel);
            nkk = kk - cumsel;
        }
        dig = __shfl_sync(0xffffffffu, dig, src);
        kk  = __shfl_sync(0xffffffffu, nkk, src);
        prefix |= dig << shift;
    }
    return prefix;
}

__global__ __launch_bounds__(256) void k3_topk(
    const float* __restrict__ attn, float* __restrict__ p2out,
    const float* __restrict__ alphas)
{
    __shared__ unsigned int hist_all[8*256];
    int wib = threadIdx.x >> 5, lane = threadIdx.x & 31;
    unsigned int* hist = &hist_all[wib*256];
    int r = blockIdx.x*8 + wib;

    const float* row = attn + (size_t)r*NPT;
    float f[13]; unsigned int u[13];
    #pragma unroll
    for (int i = 0; i < 13; i++) {
        int m = lane + 32*i;
        float v = (m < NPT) ? row[m] : NEG_INF;
        f[i] = v;
        unsigned int bb = __float_as_uint(v);
        // order-preserving float->uint; pads get 0 (below all finite values)
        u[i] = (m < NPT) ? ((bb & 0x80000000u) ? ~bb : (bb | 0x80000000u)) : 0u;
    }
    float mx = f[0];
    #pragma unroll
    for (int i = 1; i < 13; i++) mx = fmaxf(mx, f[i]);
    #pragma unroll
    for (int o = 16; o; o >>= 1) mx = fmaxf(mx, __shfl_xor_sync(0xffffffffu, mx, o));

    unsigned int t1u = warp_select_kth(u, 200u, hist, lane);  // 200th largest
    unsigned int t2u = warp_select_kth(u, 100u, hist, lane);  // 100th largest

    float l1 = 0.f, l2 = 0.f;
    #pragma unroll
    for (int i = 0; i < 13; i++) {
        float e = __expf(f[i] - mx);   // pads: exp(-inf)=0
        f[i] = e;
        if (u[i] >= t1u) { l1 += e; if (u[i] >= t2u) l2 += e; }
    }
    #pragma unroll
    for (int o = 16; o; o >>= 1) {
        l1 += __shfl_xor_sync(0xffffffffu, l1, o);
        l2 += __shfl_xor_sync(0xffffffffu, l2, o);
    }
    float i1 = 1.0f/l1, i2 = 1.0f/l2;

    float a0 = alphas[0], a1 = alphas[1];
    float am = fmaxf(a0, a1);
    float e0 = __expf(a0 - am), e1 = __expf(a1 - am);
    float al0 = e0/(e0 + e1), al1 = e1/(e0 + e1);

    float* prow = p2out + (size_t)r*NPT;
    float* wrow = g_w   + (size_t)r*NPT;
    #pragma unroll
    for (int i = 0; i < 13; i++) {
        int m = lane + 32*i;
        if (m < NPT) {
            float e  = f[i];
            float p1 = (u[i] >= t1u) ? e*i1 : 0.f;
            float p2 = (u[i] >= t2u) ? e*i2 : 0.f;
            prow[m] = p2;
            wrow[m] = al0*p1 + al1*p2;
        }
    }
}

// =====================================================================
// Kernel 4: aout = W @ V per (b,h,l). Pure tiled GEMM on precomputed g_w.
// grid (5 row-blocks of 80, 192 bhl), block 256: vg=tid&3 (4 d-dims),
// rg=tid>>2 (rows rg and rg+64).
// =====================================================================
__global__ __launch_bounds__(256) void k4_av()
{
    int nb  = blockIdx.x;            // 0..4, 80 rows each
    int bhl = blockIdx.y;
    int b = bhl / (NH*LT); int h = (bhl / LT) % NH; int l = bhl % LT;
    int blN = (b*LT + l)*NPT;

    __shared__ float Wsh[80*108];    // stride 108: conflict-free, 16B aligned
    __shared__ float Vsh[100*16];

    int tid = threadIdx.x;
    int vg = tid & 3, rg = tid >> 2;

    size_t wbase = ((size_t)bhl*NPT + nb*80)*NPT;

    float a00=0,a01=0,a02=0,a03=0;
    float a10=0,a11=0,a12=0,a13=0;

    for (int mc = 0; mc < NPT; mc += 100) {
        __syncthreads();
        for (int idx = tid; idx < 80*25; idx += 256) {
            int rr = idx/25, cc = idx%25;
            *(float4*)&Wsh[rr*108 + cc*4] =
                *(const float4*)&g_w[wbase + (size_t)rr*NPT + mc + cc*4];
        }
        for (int idx = tid; idx < 100*4; idx += 256) {
            int rr = idx >> 2, c4 = idx & 3;
            *(float4*)&Vsh[rr*16 + c4*4] =
                *(const float4*)&g_v[(size_t)(blN + mc + rr)*DM + h*HDM + c4*4];
        }
        __syncthreads();
        if (rg < 16) {
            #pragma unroll 5
            for (int ml = 0; ml < 100; ml++) {
                float4 vv = *(const float4*)&Vsh[ml*16 + vg*4];
                float w0 = Wsh[rg*108 + ml];
                float w1 = Wsh[(rg + 64)*108 + ml];
                a00 += w0*vv.x; a01 += w0*vv.y; a02 += w0*vv.z; a03 += w0*vv.w;
                a10 += w1*vv.x; a11 += w1*vv.y; a12 += w1*vv.z; a13 += w1*vv.w;
            }
        } else {
            #pragma unroll 5
            for (int ml = 0; ml < 100; ml++) {
                float4 vv = *(const float4*)&Vsh[ml*16 + vg*4];
                float w0 = Wsh[rg*108 + ml];
                a00 += w0*vv.x; a01 += w0*vv.y; a02 += w0*vv.z; a03 += w0*vv.w;
            }
        }
    }
    int n0 = nb*80 + rg;
    *(float4*)&g_aout[(size_t)(blN + n0)*DM + h*HDM + vg*4] =
        make_float4(a00, a01, a02, a03);
    if (rg < 16) {
        *(float4*)&g_aout[(size_t)(blN + n0 + 64)*DM + h*HDM + vg*4] =
            make_float4(a10, a11, a12, a13);
    }
}

// =====================================================================
// Kernel 5: epilogue per 8 tokens: Wo + LN1 + FF + LN2 + transposed store.
// block = 8 tokens, 256 threads.
// =====================================================================
__global__ __launch_bounds__(256) void k5_ffn(
    const float* __restrict__ x,
    const float* __restrict__ Wo,  const float* __restrict__ bo,
    const float* __restrict__ Wf1, const float* __restrict__ bf1,
    const float* __restrict__ Wf2, const float* __restrict__ bf2,
    const float* __restrict__ g1,  const float* __restrict__ be1,
    const float* __restrict__ g2,  const float* __restrict__ be2,
    float* __restrict__ outp)
{
    int t0 = blockIdx.x * 8;
    __shared__ float s_ao[8*128];   // attn out; later reused as FF2 partials
    __shared__ float s_xt[8*64];    // xt, then residual s1
    __shared__ float s_r1[8*64];    // LN1 out, then residual s2
    __shared__ float s_h1[8*1024];  // FF hidden
    int tid = threadIdx.x;

    for (int idx = tid; idx < 8*128; idx += 256)
        s_ao[idx] = g_aout[(size_t)t0*DM + idx];
    for (int idx = tid; idx < 8*64; idx += 256) {
        int t = t0 + (idx >> 6), c = idx & 63;
        int b = t / (LT*NPT); int rem = t % (LT*NPT);
        int l = rem / NPT;    int n = rem % NPT;
        s_xt[idx] = x[((size_t)(b*CH + c)*NPT + n)*LT + l];
    }
    __syncthreads();

    // y = ao @ Wo + bo; s1 = xt + y
    for (int o = tid; o < 8*64; o += 256) {
        int t = o >> 6, c = o & 63;
        float acc = bo[c];
        #pragma unroll 8
        for (int dd = 0; dd < 128; dd++)
            acc += s_ao[t*128 + dd] * Wo[dd*64 + c];
        s_xt[o] += acc;
    }
    __syncthreads();

    // LN1 (warp per token)
    {
        int w = tid >> 5, lane = tid & 31;
        float v0 = s_xt[w*64 + lane], v1 = s_xt[w*64 + 32 + lane];
        float sum = v0 + v1;
        #pragma unroll
        for (int o = 16; o; o >>= 1) sum += __shfl_xor_sync(0xffffffffu, sum, o);
        float mean = sum * (1.0f/64.0f);
        float d0 = v0 - mean, d1 = v1 - mean;
        float vs = d0*d0 + d1*d1;
        #pragma unroll
        for (int o = 16; o; o >>= 1) vs += __shfl_xor_sync(0xffffffffu, vs, o);
        float inv = rsqrtf(vs*(1.0f/64.0f) + EPS_LN);
        s_r1[w*64 + lane]      = d0*inv*g1[lane]      + be1[lane];
        s_r1[w*64 + 32 + lane] = d1*inv*g1[lane + 32] + be1[lane + 32];
    }
    __syncthreads();

    // FF1: h1 = relu(r1 @ Wf1 + bf1)
    for (int ff = tid; ff < FFD; ff += 256) {
        float acc[8];
        float bb = bf1[ff];
        #pragma unroll
        for (int t = 0; t < 8; t++) acc[t] = bb;
        for (int c = 0; c < 64; c++) {
            float w = Wf1[c*FFD + ff];
            #pragma unroll
            for (int t = 0; t < 8; t++) acc[t] += s_r1[t*64 + c]*w;
        }
        #pragma unroll
        for (int t = 0; t < 8; t++) s_h1[t*1024 + ff] = fmaxf(acc[t], 0.f);
    }
    __syncthreads();

    // FF2: split ff-range in 2, tokens in 2 -> partials[2][8][64]
    float facc[4] = {0.f, 0.f, 0.f, 0.f};
    int c5 = tid & 63;
    int r4 = tid >> 6;           // 0..3
    int qh = r4 & 1;             // ff half
    int th = r4 >> 1;            // token half
    for (int ff = qh*512; ff < qh*512 + 512; ff++) {
        float w = Wf2[ff*64 + c5];
        #pragma unroll
        for (int tt = 0; tt < 4; tt++)
            facc[tt] += s_h1[(th*4 + tt)*1024 + ff]*w;
    }
    __syncthreads();
    #pragma unroll
    for (int tt = 0; tt < 4; tt++)
        s_ao[qh*512 + (th*4 + tt)*64 + c5] = facc[tt];
    __syncthreads();

    // reduce partials + bias + residual
    for (int o = tid; o < 8*64; o += 256) {
        int c = o & 63;
        float y2 = bf2[c] + s_ao[o] + s_ao[512 + o];
        s_r1[o] = s_r1[o] + y2;
    }
    __syncthreads();

    // LN2 + transposed store
    {
        int w = tid >> 5, lane = tid & 31;
        float v0 = s_r1[w*64 + lane], v1 = s_r1[w*64 + 32 + lane];
        float sum = v0 + v1;
        #pragma unroll
        for (int o = 16; o; o >>= 1) sum += __shfl_xor_sync(0xffffffffu, sum, o);
        float mean = sum * (1.0f/64.0f);
        float d0 = v0 - mean, d1 = v1 - mean;
        float vs = d0*d0 + d1*d1;
        #pragma unroll
        for (int o = 16; o; o >>= 1) vs += __shfl_xor_sync(0xffffffffu, vs, o);
        float inv = rsqrtf(vs*(1.0f/64.0f) + EPS_LN);
        float o0 = d0*inv*g2[lane]      + be2[lane];
        float o1 = d1*inv*g2[lane + 32] + be2[lane + 32];

        int t = t0 + w;
        int b = t / (LT*NPT); int rem = t % (LT*NPT);
        int l = rem / NPT;    int n = rem % NPT;
        outp[((size_t)(b*CH + lane     )*NPT + n)*LT + l] = o0;
        outp[((size_t)(b*CH + lane + 32)*NPT + n)*LT + l] = o1;
    }
}

// =====================================================================
extern "C" void kernel_launch(void* const* d_in, const int* in_sizes, int n_in,
                              void* d_out, int out_size)
{
    const float* x    = (const float*)d_in[0];
    const float* xa1  = (const float*)d_in[1];
    const float* xa2  = (const float*)d_in[2];
    const float* WQ1  = (const float*)d_in[3];  const float* bQ1 = (const float*)d_in[4];
    const float* WQ2  = (const float*)d_in[5];  const float* bQ2 = (const float*)d_in[6];
    const float* WK1  = (const float*)d_in[7];  const float* bK1 = (const float*)d_in[8];
    const float* WK2  = (const float*)d_in[9];  const float* bK2 = (const float*)d_in[10];
    const float* WV   = (const float*)d_in[11]; const float* bV  = (const float*)d_in[12];
    const float* Wo   = (const float*)d_in[13]; const float* bo  = (const float*)d_in[14];
    const float* Wf1  = (const float*)d_in[15]; const float* bf1 = (const float*)d_in[16];
    const float* Wf2  = (const float*)d_in[17]; const float* bf2 = (const float*)d_in[18];
    const float* g1   = (const float*)d_in[19]; const float* be1 = (const float*)d_in[20];
    const float* g2   = (const float*)d_in[21]; const float* be2 = (const float*)d_in[22];
    const float* temp = (const float*)d_in[23];
    const float* alph = (const float*)d_in[24];

    float* outp = (float*)d_out;
    float* attn = outp + OUT0;                               // attn_flat region
    float* p2   = outp + OUT0 + (size_t)NROW*NPT;            // p2_flat region

    k1_proj<<<NTOK, 160>>>(x, xa1, xa2, WQ1, bQ1, WQ2, bQ2,
                           WK1, bK1, WK2, bK2, WV, bV);

    dim3 g2d(49, BSZ*NH*LT);
    k2_attn<<<g2d, 256>>>(attn, temp);

    k3_topk<<<NROW/8, 256>>>(attn, p2, alph);

    dim3 g4(5, BSZ*NH*LT);
    k4_av<<<g4, 256>>>();

    k5_ffn<<<NTOK/8, 256>>>(x, Wo, bo, Wf1, bf1, Wf2, bf2,
                            g1, be1, g2, be2, outp);
}

// round 9
// speedup vs baseline: 2.3245x; 1.3950x over previous
#include <cuda_runtime.h>
#include <math.h>
#include <stdint.h>

// ---------------- problem constants ----------------
#define BSZ 2
#define CH  64
#define NPT 400
#define LT  12
#define DM  128
#define NH  8
#define HDM 16
#define FFD 1024

#define NTOK (BSZ*LT*NPT)          // 9600 tokens (b,l,n)
#define NROW (BSZ*NH*LT*NPT)       // 76800 attention rows (b,h,l,n)
#define OUT0 (BSZ*CH*NPT*LT)       // 614400

#define EPS_LN 1e-5f
#define NEG_INF (__int_as_float(0xff800000))

// ---------------- scratch (device globals, no allocation) ----------------
__device__ float g_q1[NTOK*DM];
__device__ float g_q2[NTOK*DM];
__device__ float g_k1[NTOK*DM];
__device__ float g_k2[NTOK*DM];
__device__ float g_v [NTOK*DM];
__device__ float g_aout[NTOK*DM];
__device__ float g_w [(size_t)NROW*NPT];   // combined attention weights (123MB)

// =====================================================================
// Kernel 1: projections + per-head l2 norm.
// =====================================================================
__global__ __launch_bounds__(160) void k1_proj(
    const float* __restrict__ x, const float* __restrict__ xa1, const float* __restrict__ xa2,
    const float* __restrict__ WQ1, const float* __restrict__ bQ1,
    const float* __restrict__ WQ2, const float* __restrict__ bQ2,
    const float* __restrict__ WK1, const float* __restrict__ bK1,
    const float* __restrict__ WK2, const float* __restrict__ bK2,
    const float* __restrict__ WV,  const float* __restrict__ bV)
{
    int t = blockIdx.x;
    int b = t / (LT*NPT); int rem = t % (LT*NPT);
    int l = rem / NPT;    int n = rem % NPT;
    __shared__ float sh[3*CH];     // [x | xa1 | xa2]
    int tid = threadIdx.x;
    for (int idx = tid; idx < 3*CH; idx += 160) {
        int arr = idx >> 6, c = idx & 63;
        const float* src = (arr == 0) ? x : (arr == 1 ? xa1 : xa2);
        sh[idx] = src[((size_t)(b*CH + c)*NPT + n)*LT + l];
    }
    __syncthreads();

    int p = tid >> 5, dg = tid & 31;       // p uniform per warp
    const float* W    = (p==0)?WQ1 : (p==1)?WQ2 : (p==2)?WK1 : (p==3)?WK2 : WV;
    const float* bias = (p==0)?bQ1 : (p==1)?bQ2 : (p==2)?bK1 : (p==3)?bK2 : bV;
    int soff = (p==0) ? CH : (p==1 ? 2*CH : 0);

    float4 acc = *(const float4*)&bias[4*dg];
    #pragma unroll 4
    for (int c = 0; c < CH; c++) {
        float xv = sh[soff + c];
        float4 w = *(const float4*)&W[c*DM + 4*dg];
        acc.x += xv*w.x; acc.y += xv*w.y; acc.z += xv*w.z; acc.w += xv*w.w;
    }
    if (p < 4) {  // l2norm per head (head = 16 dims = 4 consecutive lanes)
        float ss = acc.x*acc.x + acc.y*acc.y + acc.z*acc.z + acc.w*acc.w;
        ss += __shfl_xor_sync(0xffffffffu, ss, 1);
        ss += __shfl_xor_sync(0xffffffffu, ss, 2);
        float inv = 1.0f / fmaxf(sqrtf(ss), 1e-12f);
        acc.x *= inv; acc.y *= inv; acc.z *= inv; acc.w *= inv;
    }
    float* dst = (p==0)?g_q1 : (p==1)?g_q2 : (p==2)?g_k1 : (p==3)?g_k2 : g_v;
    *(float4*)&dst[(size_t)t*DM + 4*dg] = acc;
}

// =====================================================================
// Kernel 2: attn[b,h,l,n,m] = temp[h]*(q1.k1 + q2.k2), written to d_out.
// =====================================================================
__global__ __launch_bounds__(256) void k2_attn(
    float* __restrict__ attn, const float* __restrict__ temperature)
{
    int tile = blockIdx.x;
    int nb = tile / 7, mb = tile % 7;
    int bhl = blockIdx.y;
    int b = bhl / (NH*LT); int h = (bhl / LT) % NH; int l = bhl % LT;
    int baset = (b*LT + l)*NPT;

    __shared__ float Qs[64*33];
    __shared__ float Ks[64*33];
    int tid = threadIdx.x;

    for (int idx = tid; idx < 64*32; idx += 256) {
        int row = idx >> 5, kk = idx & 31;
        int n = nb*64 + row, m = mb*64 + row;
        float qv = 0.f, kv = 0.f;
        if (n < NPT) {
            size_t base = (size_t)(baset + n)*DM + h*HDM;
            qv = (kk < 16) ? g_q1[base + kk] : g_q2[base + kk - 16];
        }
        if (m < NPT) {
            size_t base = (size_t)(baset + m)*DM + h*HDM;
            kv = (kk < 16) ? g_k1[base + kk] : g_k2[base + kk - 16];
        }
        Qs[row*33 + kk] = qv;
        Ks[row*33 + kk] = kv;
    }
    __syncthreads();

    int tx = tid & 15, ty = tid >> 4;
    float acc[4][4] = {};
    #pragma unroll
    for (int kk = 0; kk < 32; kk++) {
        float qr[4], kr[4];
        #pragma unroll
        for (int i = 0; i < 4; i++) qr[i] = Qs[(ty + 16*i)*33 + kk];
        #pragma unroll
        for (int j = 0; j < 4; j++) kr[j] = Ks[(tx + 16*j)*33 + kk];
        #pragma unroll
        for (int i = 0; i < 4; i++)
            #pragma unroll
            for (int j = 0; j < 4; j++) acc[i][j] += qr[i]*kr[j];
    }

    float temp = temperature[h];
    size_t base = (size_t)bhl * NPT * NPT;
    #pragma unroll
    for (int i = 0; i < 4; i++) {
        int n = nb*64 + ty + 16*i;
        if (n >= NPT) continue;
        #pragma unroll
        for (int j = 0; j < 4; j++) {
            int m = mb*64 + tx + 16*j;
            if (m < NPT) attn[base + (size_t)n*NPT + m] = acc[i][j]*temp;
        }
    }
}

// =====================================================================
// Kernel 3: warp-per-row EXACT k-th order statistic via range-quantized
// bucket select: ONE full 256-bin atomic histogram shared by both k=200
// and k=100 walks; <=3 cheap refinement passes (few active lanes).
// Then softmax sums, write p2_flat and combined weight into g_w.
// =====================================================================
__device__ __forceinline__ void walk_bins(
    const unsigned int c[8], unsigned int k, int lane,
    unsigned int& bsel, unsigned int& krem)
{
    // lane owns buckets [lane*8, lane*8+8); find bucket holding k-th LARGEST
    unsigned int lsum = 0;
    #pragma unroll
    for (int b = 0; b < 8; b++) lsum += c[b];
    unsigned int s = lsum;                       // suffix sum over lanes >= lane
    #pragma unroll
    for (int o = 1; o < 32; o <<= 1) {
        unsigned int t = __shfl_down_sync(0xffffffffu, s, o);
        if (lane + o < 32) s += t;
    }
    unsigned int excl = __shfl_down_sync(0xffffffffu, s, 1);
    if (lane == 31) excl = 0u;
    unsigned int ball = __ballot_sync(0xffffffffu, (excl < k) && (excl + lsum >= k));
    int src = __ffs((int)ball) - 1;
    unsigned int dig = 0, nk = 0;
    if (lane == src) {
        unsigned int cum = excl, cumsel = excl;
        int bs = 0; bool fnd = false;
        #pragma unroll
        for (int b = 7; b >= 0; b--) {
            if (!fnd && (cum + c[b] >= k)) { bs = b; cumsel = cum; fnd = true; }
            if (!fnd) cum += c[b];
        }
        dig = (unsigned)(lane*8 + bs);
        nk  = k - cumsel;
    }
    bsel = __shfl_sync(0xffffffffu, dig, src);
    krem = __shfl_sync(0xffffffffu, nk,  src);
}

__device__ __forceinline__ unsigned int select_kth(
    const unsigned int u[13], int lane, unsigned int* hist,
    unsigned int lo, int shift, const unsigned int c0[8], unsigned int k)
{
    unsigned int bsel, krem;
    walk_bins(c0, k, lane, bsel, krem);
    lo += bsel << shift;
    k = krem;
    while (shift > 0) {                      // warp-uniform
        int ns = (shift > 8) ? shift - 8 : 0;
        unsigned int hi2 = lo + ((1u << shift) - 1u);
        #pragma unroll
        for (int b = 0; b < 8; b++) hist[lane*8 + b] = 0u;
        __syncwarp();
        #pragma unroll
        for (int i = 0; i < 13; i++) {
            unsigned int key = u[i];
            if (key >= lo && key <= hi2)
                atomicAdd(&hist[(key - lo) >> ns], 1u);
        }
        __syncwarp();
        unsigned int c[8];
        #pragma unroll
        for (int b = 0; b < 8; b++) c[b] = hist[lane*8 + b];
        __syncwarp();
        walk_bins(c, k, lane, bsel, krem);
        lo += bsel << ns;
        k = krem;
        shift = ns;
    }
    return lo;   // exact key of k-th largest
}

__global__ __launch_bounds__(256) void k3_topk(
    const float* __restrict__ attn, float* __restrict__ p2out,
    const float* __restrict__ alphas)
{
    __shared__ unsigned int hist_all[8*256];
    int wib = threadIdx.x >> 5, lane = threadIdx.x & 31;
    unsigned int* hist = &hist_all[wib*256];
    int r = blockIdx.x*8 + wib;

    const float* row = attn + (size_t)r*NPT;
    float f[13]; unsigned int u[13];
    #pragma unroll
    for (int i = 0; i < 13; i++) {
        int m = lane + 32*i;
        float v = (m < NPT) ? row[m] : NEG_INF;
        f[i] = v;
        unsigned int bb = __float_as_uint(v);
        unsigned int key = (bb & 0x80000000u) ? ~bb : (bb | 0x80000000u);
        u[i] = (m < NPT) ? key : 0u;        // pads: key 0, excluded everywhere
    }
    float mx = NEG_INF;
    unsigned int lo = 0xFFFFFFFFu, hi = 0u;
    #pragma unroll
    for (int i = 0; i < 13; i++) {
        int m = lane + 32*i;
        if (m < NPT) {
            mx = fmaxf(mx, f[i]);
            lo = min(lo, u[i]);
            hi = max(hi, u[i]);
        }
    }
    #pragma unroll
    for (int o = 16; o; o >>= 1) {
        mx = fmaxf(mx, __shfl_xor_sync(0xffffffffu, mx, o));
        lo = min(lo, __shfl_xor_sync(0xffffffffu, lo, o));
        hi = max(hi, __shfl_xor_sync(0xffffffffu, hi, o));
    }
    unsigned int range = hi - lo;
    int rb = (range == 0u) ? 0 : (32 - __clz(range));
    int shift = (rb > 8) ? rb - 8 : 0;

    // single full histogram pass (shared by both selects)
    #pragma unroll
    for (int b = 0; b < 8; b++) hist[lane*8 + b] = 0u;
    __syncwarp();
    #pragma unroll
    for (int i = 0; i < 13; i++) {
        int m = lane + 32*i;
        if (m < NPT) atomicAdd(&hist[(u[i] - lo) >> shift], 1u);
    }
    __syncwarp();
    unsigned int c0[8];
    #pragma unroll
    for (int b = 0; b < 8; b++) c0[b] = hist[lane*8 + b];
    __syncwarp();

    unsigned int t1u = select_kth(u, lane, hist, lo, shift, c0, 200u);
    unsigned int t2u = select_kth(u, lane, hist, lo, shift, c0, 100u);

    float l1 = 0.f, l2 = 0.f;
    #pragma unroll
    for (int i = 0; i < 13; i++) {
        float e = __expf(f[i] - mx);        // pads: exp(-inf)=0
        f[i] = e;
        if (u[i] >= t1u) { l1 += e; if (u[i] >= t2u) l2 += e; }
    }
    #pragma unroll
    for (int o = 16; o; o >>= 1) {
        l1 += __shfl_xor_sync(0xffffffffu, l1, o);
        l2 += __shfl_xor_sync(0xffffffffu, l2, o);
    }
    float i1 = 1.0f/l1, i2 = 1.0f/l2;

    float a0 = alphas[0], a1 = alphas[1];
    float am = fmaxf(a0, a1);
    float e0 = __expf(a0 - am), e1 = __expf(a1 - am);
    float al0 = e0/(e0 + e1), al1 = e1/(e0 + e1);

    float* prow = p2out + (size_t)r*NPT;
    float* wrow = g_w   + (size_t)r*NPT;
    #pragma unroll
    for (int i = 0; i < 13; i++) {
        int m = lane + 32*i;
        if (m < NPT) {
            float e  = f[i];
            float p1 = (u[i] >= t1u) ? e*i1 : 0.f;
            float p2 = (u[i] >= t2u) ? e*i2 : 0.f;
            prow[m] = p2;
            wrow[m] = al0*p1 + al1*p2;
        }
    }
}

// =====================================================================
// Kernel 4: aout = W @ V per (b,h,l). Tiled GEMM, float4 W loads (halved
// LDS issue vs scalar). grid (5 x 192), block 256.
// =====================================================================
__global__ __launch_bounds__(256) void k4_av()
{
    int nb  = blockIdx.x;            // 0..4, 80 rows each
    int bhl = blockIdx.y;
    int b = bhl / (NH*LT); int h = (bhl / LT) % NH; int l = bhl % LT;
    int blN = (b*LT + l)*NPT;

    __shared__ float Wsh[80*108];    // stride 108 (432B): float4-aligned, bank-clean
    __shared__ float Vsh[100*16];

    int tid = threadIdx.x;
    int vg = tid & 3, rg = tid >> 2;

    size_t wbase = ((size_t)bhl*NPT + nb*80)*NPT;

    float a00=0,a01=0,a02=0,a03=0;
    float a10=0,a11=0,a12=0,a13=0;

    for (int mc = 0; mc < NPT; mc += 100) {
        __syncthreads();
        for (int idx = tid; idx < 80*25; idx += 256) {
            int rr = idx/25, cc = idx%25;
            *(float4*)&Wsh[rr*108 + cc*4] =
                *(const float4*)&g_w[wbase + (size_t)rr*NPT + mc + cc*4];
        }
        for (int idx = tid; idx < 100*4; idx += 256) {
            int rr = idx >> 2, c4 = idx & 3;
            *(float4*)&Vsh[rr*16 + c4*4] =
                *(const float4*)&g_v[(size_t)(blN + mc + rr)*DM + h*HDM + c4*4];
        }
        __syncthreads();
        if (rg < 16) {
            #pragma unroll 5
            for (int ml = 0; ml < 100; ml += 4) {
                float4 w0 = *(const float4*)&Wsh[rg*108 + ml];
                float4 w1 = *(const float4*)&Wsh[(rg + 64)*108 + ml];
                float4 v0 = *(const float4*)&Vsh[(ml+0)*16 + vg*4];
                float4 v1 = *(const float4*)&Vsh[(ml+1)*16 + vg*4];
                float4 v2 = *(const float4*)&Vsh[(ml+2)*16 + vg*4];
                float4 v3 = *(const float4*)&Vsh[(ml+3)*16 + vg*4];
                a00 += w0.x*v0.x + w0.y*v1.x + w0.z*v2.x + w0.w*v3.x;
                a01 += w0.x*v0.y + w0.y*v1.y + w0.z*v2.y + w0.w*v3.y;
                a02 += w0.x*v0.z + w0.y*v1.z + w0.z*v2.z + w0.w*v3.z;
                a03 += w0.x*v0.w + w0.y*v1.w + w0.z*v2.w + w0.w*v3.w;
                a10 += w1.x*v0.x + w1.y*v1.x + w1.z*v2.x + w1.w*v3.x;
                a11 += w1.x*v0.y + w1.y*v1.y + w1.z*v2.y + w1.w*v3.y;
                a12 += w1.x*v0.z + w1.y*v1.z + w1.z*v2.z + w1.w*v3.z;
                a13 += w1.x*v0.w + w1.y*v1.w + w1.z*v2.w + w1.w*v3.w;
            }
        } else {
            #pragma unroll 5
            for (int ml = 0; ml < 100; ml += 4) {
                float4 w0 = *(const float4*)&Wsh[rg*108 + ml];
                float4 v0 = *(const float4*)&Vsh[(ml+0)*16 + vg*4];
                float4 v1 = *(const float4*)&Vsh[(ml+1)*16 + vg*4];
                float4 v2 = *(const float4*)&Vsh[(ml+2)*16 + vg*4];
                float4 v3 = *(const float4*)&Vsh[(ml+3)*16 + vg*4];
                a00 += w0.x*v0.x + w0.y*v1.x + w0.z*v2.x + w0.w*v3.x;
                a01 += w0.x*v0.y + w0.y*v1.y + w0.z*v2.y + w0.w*v3.y;
                a02 += w0.x*v0.z + w0.y*v1.z + w0.z*v2.z + w0.w*v3.z;
                a03 += w0.x*v0.w + w0.y*v1.w + w0.z*v2.w + w0.w*v3.w;
            }
        }
    }
    int n0 = nb*80 + rg;
    *(float4*)&g_aout[(size_t)(blN + n0)*DM + h*HDM + vg*4] =
        make_float4(a00, a01, a02, a03);
    if (rg < 16) {
        *(float4*)&g_aout[(size_t)(blN + n0 + 64)*DM + h*HDM + vg*4] =
            make_float4(a10, a11, a12, a13);
    }
}

// =====================================================================
// Kernel 5: epilogue per 8 tokens: Wo + LN1 + FF + LN2 + transposed store.
// =====================================================================
__global__ __launch_bounds__(256) void k5_ffn(
    const float* __restrict__ x,
    const float* __restrict__ Wo,  const float* __restrict__ bo,
    const float* __restrict__ Wf1, const float* __restrict__ bf1,
    const float* __restrict__ Wf2, const float* __restrict__ bf2,
    const float* __restrict__ g1,  const float* __restrict__ be1,
    const float* __restrict__ g2,  const float* __restrict__ be2,
    float* __restrict__ outp)
{
    int t0 = blockIdx.x * 8;
    __shared__ float s_ao[8*128];   // attn out; later reused as FF2 partials
    __shared__ float s_xt[8*64];    // xt, then residual s1
    __shared__ float s_r1[8*64];    // LN1 out, then residual s2
    __shared__ float s_h1[8*1024];  // FF hidden
    int tid = threadIdx.x;

    for (int idx = tid; idx < 8*128; idx += 256)
        s_ao[idx] = g_aout[(size_t)t0*DM + idx];
    for (int idx = tid; idx < 8*64; idx += 256) {
        int t = t0 + (idx >> 6), c = idx & 63;
        int b = t / (LT*NPT); int rem = t % (LT*NPT);
        int l = rem / NPT;    int n = rem % NPT;
        s_xt[idx] = x[((size_t)(b*CH + c)*NPT + n)*LT + l];
    }
    __syncthreads();

    // y = ao @ Wo + bo; s1 = xt + y
    for (int o = tid; o < 8*64; o += 256) {
        int t = o >> 6, c = o & 63;
        float acc = bo[c];
        #pragma unroll 8
        for (int dd = 0; dd < 128; dd++)
            acc += s_ao[t*128 + dd] * Wo[dd*64 + c];
        s_xt[o] += acc;
    }
    __syncthreads();

    // LN1 (warp per token)
    {
        int w = tid >> 5, lane = tid & 31;
        float v0 = s_xt[w*64 + lane], v1 = s_xt[w*64 + 32 + lane];
        float sum = v0 + v1;
        #pragma unroll
        for (int o = 16; o; o >>= 1) sum += __shfl_xor_sync(0xffffffffu, sum, o);
        float mean = sum * (1.0f/64.0f);
        float d0 = v0 - mean, d1 = v1 - mean;
        float vs = d0*d0 + d1*d1;
        #pragma unroll
        for (int o = 16; o; o >>= 1) vs += __shfl_xor_sync(0xffffffffu, vs, o);
        float inv = rsqrtf(vs*(1.0f/64.0f) + EPS_LN);
        s_r1[w*64 + lane]      = d0*inv*g1[lane]      + be1[lane];
        s_r1[w*64 + 32 + lane] = d1*inv*g1[lane + 32] + be1[lane + 32];
    }
    __syncthreads();

    // FF1: h1 = relu(r1 @ Wf1 + bf1)
    for (int ff = tid; ff < FFD; ff += 256) {
        float acc[8];
        float bb = bf1[ff];
        #pragma unroll
        for (int t = 0; t < 8; t++) acc[t] = bb;
        for (int c = 0; c < 64; c++) {
            float w = Wf1[c*FFD + ff];
            #pragma unroll
            for (int t = 0; t < 8; t++) acc[t] += s_r1[t*64 + c]*w;
        }
        #pragma unroll
        for (int t = 0; t < 8; t++) s_h1[t*1024 + ff] = fmaxf(acc[t], 0.f);
    }
    __syncthreads();

    // FF2: split ff-range in 2, tokens in 2 -> partials[2][8][64]
    float facc[4] = {0.f, 0.f, 0.f, 0.f};
    int c5 = tid & 63;
    int r4 = tid >> 6;           // 0..3
    int qh = r4 & 1;             // ff half
    int th = r4 >> 1;            // token half
    for (int ff = qh*512; ff < qh*512 + 512; ff++) {
        float w = Wf2[ff*64 + c5];
        #pragma unroll
        for (int tt = 0; tt < 4; tt++)
            facc[tt] += s_h1[(th*4 + tt)*1024 + ff]*w;
    }
    __syncthreads();
    #pragma unroll
    for (int tt = 0; tt < 4; tt++)
        s_ao[qh*512 + (th*4 + tt)*64 + c5] = facc[tt];
    __syncthreads();

    // reduce partials + bias + residual
    for (int o = tid; o < 8*64; o += 256) {
        int c = o & 63;
        float y2 = bf2[c] + s_ao[o] + s_ao[512 + o];
        s_r1[o] = s_r1[o] + y2;
    }
    __syncthreads();

    // LN2 + transposed store
    {
        int w = tid >> 5, lane = tid & 31;
        float v0 = s_r1[w*64 + lane], v1 = s_r1[w*64 + 32 + lane];
        float sum = v0 + v1;
        #pragma unroll
        for (int o = 16; o; o >>= 1) sum += __shfl_xor_sync(0xffffffffu, sum, o);
        float mean = sum * (1.0f/64.0f);
        float d0 = v0 - mean, d1 = v1 - mean;
        float vs = d0*d0 + d1*d1;
        #pragma unroll
        for (int o = 16; o; o >>= 1) vs += __shfl_xor_sync(0xffffffffu, vs, o);
        float inv = rsqrtf(vs*(1.0f/64.0f) + EPS_LN);
        float o0 = d0*inv*g2[lane]      + be2[lane];
        float o1 = d1*inv*g2[lane + 32] + be2[lane + 32];

        int t = t0 + w;
        int b = t / (LT*NPT); int rem = t % (LT*NPT);
        int l = rem / NPT;    int n = rem % NPT;
        outp[((size_t)(b*CH + lane     )*NPT + n)*LT + l] = o0;
        outp[((size_t)(b*CH + lane + 32)*NPT + n)*LT + l] = o1;
    }
}

// =====================================================================
extern "C" void kernel_launch(void* const* d_in, const int* in_sizes, int n_in,
                              void* d_out, int out_size)
{
    const float* x    = (const float*)d_in[0];
    const float* xa1  = (const float*)d_in[1];
    const float* xa2  = (const float*)d_in[2];
    const float* WQ1  = (const float*)d_in[3];  const float* bQ1 = (const float*)d_in[4];
    const float* WQ2  = (const float*)d_in[5];  const float* bQ2 = (const float*)d_in[6];
    const float* WK1  = (const float*)d_in[7];  const float* bK1 = (const float*)d_in[8];
    const float* WK2  = (const float*)d_in[9];  const float* bK2 = (const float*)d_in[10];
    const float* WV   = (const float*)d_in[11]; const float* bV  = (const float*)d_in[12];
    const float* Wo   = (const float*)d_in[13]; const float* bo  = (const float*)d_in[14];
    const float* Wf1  = (const float*)d_in[15]; const float* bf1 = (const float*)d_in[16];
    const float* Wf2  = (const float*)d_in[17]; const float* bf2 = (const float*)d_in[18];
    const float* g1   = (const float*)d_in[19]; const float* be1 = (const float*)d_in[20];
    const float* g2   = (const float*)d_in[21]; const float* be2 = (const float*)d_in[22];
    const float* temp = (const float*)d_in[23];
    const float* alph = (const float*)d_in[24];

    float* outp = (float*)d_out;
    float* attn = outp + OUT0;                               // attn_flat region
    float* p2   = outp + OUT0 + (size_t)NROW*NPT;            // p2_flat region

    k1_proj<<<NTOK, 160>>>(x, xa1, xa2, WQ1, bQ1, WQ2, bQ2,
                           WK1, bK1, WK2, bK2, WV, bV);

    dim3 g2d(49, BSZ*NH*LT);
    k2_attn<<<g2d, 256>>>(attn, temp);

    k3_topk<<<NROW/8, 256>>>(attn, p2, alph);

    dim3 g4(5, BSZ*NH*LT);
    k4_av<<<g4, 256>>>();

    k5_ffn<<<NTOK/8, 256>>>(x, Wo, bo, Wf1, bf1, Wf2, bf2,
                            g1, be1, g2, be2, outp);
}